// round 7
// baseline (speedup 1.0000x reference)
#include <cuda_runtime.h>

// S4D kernel: K[h,l] = 2 * Re( sum_n Cmod[h,n] * exp(dtA[h,n] * l) ),
// H=1024, N=64, L=2048.
//
// Modes merged in pairs: s_k = r_k[n] + r_k[n+1] obeys an ORDER-4 real
// recurrence s_{k+4} = c3 s_{k+3} + c2 s_{k+2} + c1 s_{k+1} + c0 s_k
// (char poly = product of the two mode quadratics; all |roots|<1).
//
// One block (128 thr, 4 warps) per h; lane owns l = lane + 32k, 64 k.
// Warp w owns n in [16w,16w+16) = 8 merged streams = 4 packed f32x2
// stream-pairs. Single-wave residency: 7 blocks/SM (launch_bounds(128,7),
// smem ~12KB) so all 1024 blocks run concurrently — no ragged wave-2 tail.
// Partials buffered 16 k at a time (8KB), 4 chunks.

#define N_      64
#define WARPS   4
#define SP      4              // packed stream-pairs per thread
#define CHUNK_K 16             // k-steps per chunk
#define CHUNKS  4

typedef unsigned long long u64;

__device__ __forceinline__ u64 pack2(float lo, float hi) {
    u64 r; asm("mov.b64 %0, {%1,%2};" : "=l"(r) : "f"(lo), "f"(hi)); return r;
}
__device__ __forceinline__ void unpack2(u64 v, float& lo, float& hi) {
    asm("mov.b64 {%0,%1}, %2;" : "=f"(lo), "=f"(hi) : "l"(v));
}
__device__ __forceinline__ u64 fma2(u64 a, u64 b, u64 c) {
    u64 d; asm("fma.rn.f32x2 %0,%1,%2,%3;" : "=l"(d) : "l"(a), "l"(b), "l"(c)); return d;
}
__device__ __forceinline__ u64 mul2(u64 a, u64 b) {
    u64 d; asm("mul.rn.f32x2 %0,%1,%2;" : "=l"(d) : "l"(a), "l"(b)); return d;
}
__device__ __forceinline__ u64 add2(u64 a, u64 b) {
    u64 d; asm("add.rn.f32x2 %0,%1,%2;" : "=l"(d) : "l"(a), "l"(b)); return d;
}

__global__ __launch_bounds__(128, 7)
void s4d_fused(const float* __restrict__ log_dt,
               const float* __restrict__ C,
               const float* __restrict__ A,
               float* __restrict__ out, int L)
{
    __shared__ float2 s_dta[N_], s_cm[N_], s_w32[N_], s_pq[N_];
    __shared__ float4 s_c4[N_ / 2];                 // order-4 coeffs per merged pair
    __shared__ u64    s_part[CHUNK_K][WARPS][32];   // packed partials, 8KB

    const int h    = blockIdx.x;
    const int tid  = threadIdx.x;
    const int wid  = tid >> 5;
    const int lane = tid & 31;

    // ---- per-n parameter precompute (threads 0..63, one n each) ----
    if (tid < N_) {
        int n = tid;
        float dt  = expf(log_dt[h]);
        float ar  = A[2 * n], ai = A[2 * n + 1];
        float dre = dt * ar, dim = dt * ai;

        float e1 = expf(dre); float s1, c1; sincosf(dim, &s1, &c1);
        float w1r = e1 * c1, w1i = e1 * s1;

        float inv = 1.0f / (ar * ar + ai * ai);
        float nr = w1r - 1.0f, ni = w1i;
        float qdr = (nr * ar + ni * ai) * inv;
        float qdi = (ni * ar - nr * ai) * inv;

        float cr = C[2 * (h * N_ + n)], ci = C[2 * (h * N_ + n) + 1];
        float cmr = 2.0f * (cr * qdr - ci * qdi);
        float cmi = 2.0f * (cr * qdi + ci * qdr);

        float e32 = expf(32.0f * dre); float s32, c32; sincosf(32.0f * dim, &s32, &c32);
        float wr = e32 * c32, wi = e32 * s32;

        s_dta[n] = make_float2(dre, dim);
        s_cm [n] = make_float2(cmr, cmi);
        s_w32[n] = make_float2(wr, wi);
        s_pq [n] = make_float2(2.0f * wr, -(wr * wr + wi * wi));
    }
    __syncthreads();

    // ---- merged order-4 coefficients: (x^2 - p1 x - q1)(x^2 - p2 x - q2) ----
    if (tid < N_ / 2) {
        float2 a = s_pq[2 * tid], b = s_pq[2 * tid + 1];
        float c3 = a.x + b.x;
        float c2 = a.y + b.y - a.x * b.x;
        float c1 = -(a.x * b.y + b.x * a.y);
        float c0 = -a.y * b.y;
        s_c4[tid] = make_float4(c0, c1, c2, c3);
    }
    __syncthreads();

    // ---- per-thread state init: per mode z = cm*exp(dtA*lane); first 4
    //      merged samples s_0..s_3 by complex stepping ----
    const float lf = (float)lane;
    const int   n0 = wid * 16;

    u64 S0[SP], S1[SP], S2[SP], S3[SP];
    u64 C0[SP], C1[SP], C2[SP], C3[SP];

#pragma unroll
    for (int j = 0; j < SP; j++) {
        float sm[2][4];
#pragma unroll
        for (int t = 0; t < 2; t++) {
            int ns = n0 + 2 * (2 * j + t);
            float acc[4] = {0.f, 0.f, 0.f, 0.f};
#pragma unroll
            for (int u = 0; u < 2; u++) {
                int n = ns + u;
                float2 d = s_dta[n];
                float ex = expf(d.x * lf);
                float s, c; sincosf(d.y * lf, &s, &c);
                float er = ex * c, ei = ex * s;
                float2 cm = s_cm[n];
                float zr = cm.x * er - cm.y * ei;
                float zi = cm.x * ei + cm.y * er;
                float2 w = s_w32[n];
#pragma unroll
                for (int k = 0; k < 4; k++) {
                    acc[k] += zr;
                    float tr = zr * w.x - zi * w.y;
                    float ti = zr * w.y + zi * w.x;
                    zr = tr; zi = ti;
                }
            }
#pragma unroll
            for (int k = 0; k < 4; k++) sm[t][k] = acc[k];
        }
        S0[j] = pack2(sm[0][0], sm[1][0]);
        S1[j] = pack2(sm[0][1], sm[1][1]);
        S2[j] = pack2(sm[0][2], sm[1][2]);
        S3[j] = pack2(sm[0][3], sm[1][3]);

        float4 ca = s_c4[(n0 >> 1) + 2 * j];
        float4 cb = s_c4[(n0 >> 1) + 2 * j + 1];
        C0[j] = pack2(ca.x, cb.x);
        C1[j] = pack2(ca.y, cb.y);
        C2[j] = pack2(ca.z, cb.z);
        C3[j] = pack2(ca.w, cb.w);
    }

    float* orow = out + (size_t)h * L;
    u64*   s_slot = &s_part[0][wid][lane];

#pragma unroll 1
    for (int ch = 0; ch < CHUNKS; ch++) {
        if (ch) __syncthreads();            // buffer reusable

#pragma unroll 1
        for (int k4 = 0; k4 < CHUNK_K; k4 += 4) {
#pragma unroll
            for (int kk = 0; kk < 4; kk++) {
                u64 a0, a1;
                if (kk == 0) {
                    a0 = add2(S0[0], S0[1]); a1 = add2(S0[2], S0[3]);
#pragma unroll
                    for (int j = 0; j < SP; j++)
                        S0[j] = fma2(C3[j], S3[j], fma2(C2[j], S2[j],
                                 fma2(C1[j], S1[j], mul2(C0[j], S0[j]))));
                } else if (kk == 1) {
                    a0 = add2(S1[0], S1[1]); a1 = add2(S1[2], S1[3]);
#pragma unroll
                    for (int j = 0; j < SP; j++)
                        S1[j] = fma2(C3[j], S0[j], fma2(C2[j], S3[j],
                                 fma2(C1[j], S2[j], mul2(C0[j], S1[j]))));
                } else if (kk == 2) {
                    a0 = add2(S2[0], S2[1]); a1 = add2(S2[2], S2[3]);
#pragma unroll
                    for (int j = 0; j < SP; j++)
                        S2[j] = fma2(C3[j], S1[j], fma2(C2[j], S0[j],
                                 fma2(C1[j], S3[j], mul2(C0[j], S2[j]))));
                } else {
                    a0 = add2(S3[0], S3[1]); a1 = add2(S3[2], S3[3]);
#pragma unroll
                    for (int j = 0; j < SP; j++)
                        S3[j] = fma2(C3[j], S2[j], fma2(C2[j], S1[j],
                                 fma2(C1[j], S0[j], mul2(C0[j], S3[j]))));
                }
                s_slot[(size_t)(k4 + kk) * (WARPS * 32)] = add2(a0, a1);
            }
        }
        __syncthreads();

        // ---- cross-warp reduction: warp w handles k = w + 4i ----
#pragma unroll
        for (int i = 0; i < CHUNK_K / WARPS; i++) {
            int k = wid + WARPS * i;
            float sum = 0.0f;
#pragma unroll
            for (int w = 0; w < WARPS; w++) {
                float lo, hi;
                unpack2(s_part[k][w][lane], lo, hi);
                sum += lo + hi;
            }
            orow[(size_t)(ch * CHUNK_K + k) * 32 + lane] = sum;
        }
    }
}

extern "C" void kernel_launch(void* const* d_in, const int* in_sizes, int n_in,
                              void* d_out, int out_size)
{
    const float* log_dt = (const float*)d_in[0];
    const float* C      = (const float*)d_in[1];
    const float* A      = (const float*)d_in[2];
    // d_in[3] = input_length scalar; L derived from out_size.

    int H = in_sizes[0];          // 1024
    int L = out_size / H;         // 2048

    s4d_fused<<<H, 128>>>(log_dt, C, A, (float*)d_out, L);
}

// round 8
// speedup vs baseline: 1.0851x; 1.0851x over previous
#include <cuda_runtime.h>

// S4D kernel: K[h,l] = 2 * Re( sum_n Cmod[h,n] * exp(dtA[h,n] * l) ),
// H=1024, N=64, L=2048.
//
// Modes merged in pairs: s_k = r_k[n] + r_k[n+1] obeys an ORDER-4 real
// recurrence s_{k+4} = c3 s_{k+3} + c2 s_{k+2} + c1 s_{k+1} + c0 s_k
// (char poly = product of the two mode quadratics; all |roots|<1 => stable).
// Cost: 2 scalar fma-ops per (mode, k) — the asymptotic minimum for this
// recurrence family. SCALAR FFMA only (measured: packed f32x2 is
// throughput-neutral on sm_103a).
//
// One block (128 thr, 4 warps) per h; lane owns l = lane + 32k, 64 k.
// Warp w owns n in [16w,16w+16) = 8 merged streams per thread (scalar).
// Barrier-free main loop; per-k scalar partials in an 8KB buffer per
// 16-k chunk; 4 chunks, 2 barriers each.

#define N_      64
#define WARPS   4
#define NS      8              // merged streams per thread (2 modes each)
#define CHUNK_K 16             // k-steps per chunk
#define CHUNKS  4

__global__ __launch_bounds__(128)
void s4d_fused(const float* __restrict__ log_dt,
               const float* __restrict__ C,
               const float* __restrict__ A,
               float* __restrict__ out, int L)
{
    __shared__ float2 s_dta[N_], s_cm[N_], s_w32[N_], s_pq[N_];
    __shared__ float4 s_c4[N_ / 2];                // order-4 coeffs per merged pair
    __shared__ float  s_part[CHUNK_K][WARPS][32];  // scalar partials, 8KB

    const int h    = blockIdx.x;
    const int tid  = threadIdx.x;
    const int wid  = tid >> 5;
    const int lane = tid & 31;

    // ---- per-n parameter precompute (threads 0..63, one n each) ----
    if (tid < N_) {
        int n = tid;
        float dt  = expf(log_dt[h]);
        float ar  = A[2 * n], ai = A[2 * n + 1];
        float dre = dt * ar, dim = dt * ai;

        float e1 = expf(dre); float s1, c1; sincosf(dim, &s1, &c1);
        float w1r = e1 * c1, w1i = e1 * s1;

        float inv = 1.0f / (ar * ar + ai * ai);
        float nr = w1r - 1.0f, ni = w1i;
        float qdr = (nr * ar + ni * ai) * inv;
        float qdi = (ni * ar - nr * ai) * inv;

        float cr = C[2 * (h * N_ + n)], ci = C[2 * (h * N_ + n) + 1];
        float cmr = 2.0f * (cr * qdr - ci * qdi);
        float cmi = 2.0f * (cr * qdi + ci * qdr);

        float e32 = expf(32.0f * dre); float s32, c32; sincosf(32.0f * dim, &s32, &c32);
        float wr = e32 * c32, wi = e32 * s32;

        s_dta[n] = make_float2(dre, dim);
        s_cm [n] = make_float2(cmr, cmi);
        s_w32[n] = make_float2(wr, wi);
        s_pq [n] = make_float2(2.0f * wr, -(wr * wr + wi * wi));
    }
    __syncthreads();

    // ---- merged order-4 coefficients: (x^2 - p1 x - q1)(x^2 - p2 x - q2) ----
    if (tid < N_ / 2) {
        float2 a = s_pq[2 * tid], b = s_pq[2 * tid + 1];
        float c3 = a.x + b.x;
        float c2 = a.y + b.y - a.x * b.x;
        float c1 = -(a.x * b.y + b.x * a.y);
        float c0 = -a.y * b.y;
        s_c4[tid] = make_float4(c0, c1, c2, c3);
    }
    __syncthreads();

    // ---- per-thread state init: per mode z = cm*exp(dtA*lane); first 4
    //      merged samples s_0..s_3 by complex stepping ----
    const float lf = (float)lane;
    const int   n0 = wid * 16;

    float S0[NS], S1[NS], S2[NS], S3[NS];
    float C0[NS], C1[NS], C2[NS], C3[NS];

#pragma unroll
    for (int j = 0; j < NS; j++) {
        int ns = n0 + 2 * j;
        float acc[4] = {0.f, 0.f, 0.f, 0.f};
#pragma unroll
        for (int u = 0; u < 2; u++) {
            int n = ns + u;
            float2 d = s_dta[n];
            float ex = expf(d.x * lf);
            float s, c; sincosf(d.y * lf, &s, &c);
            float er = ex * c, ei = ex * s;
            float2 cm = s_cm[n];
            float zr = cm.x * er - cm.y * ei;
            float zi = cm.x * ei + cm.y * er;
            float2 w = s_w32[n];
#pragma unroll
            for (int k = 0; k < 4; k++) {
                acc[k] += zr;
                float tr = zr * w.x - zi * w.y;
                float ti = zr * w.y + zi * w.x;
                zr = tr; zi = ti;
            }
        }
        S0[j] = acc[0]; S1[j] = acc[1]; S2[j] = acc[2]; S3[j] = acc[3];

        float4 cc = s_c4[(n0 >> 1) + j];
        C0[j] = cc.x; C1[j] = cc.y; C2[j] = cc.z; C3[j] = cc.w;
    }

    float* orow  = out + (size_t)h * L;
    float* s_slot = &s_part[0][wid][lane];

#pragma unroll 1
    for (int ch = 0; ch < CHUNKS; ch++) {
        if (ch) __syncthreads();            // buffer reusable

#pragma unroll 1
        for (int k4 = 0; k4 < CHUNK_K; k4 += 4) {
#pragma unroll
            for (int kk = 0; kk < 4; kk++) {
                float a;
                if (kk == 0) {
                    a = ((S0[0] + S0[1]) + (S0[2] + S0[3]))
                      + ((S0[4] + S0[5]) + (S0[6] + S0[7]));
#pragma unroll
                    for (int j = 0; j < NS; j++)
                        S0[j] = fmaf(C3[j], S3[j], fmaf(C2[j], S2[j],
                                 fmaf(C1[j], S1[j], C0[j] * S0[j])));
                } else if (kk == 1) {
                    a = ((S1[0] + S1[1]) + (S1[2] + S1[3]))
                      + ((S1[4] + S1[5]) + (S1[6] + S1[7]));
#pragma unroll
                    for (int j = 0; j < NS; j++)
                        S1[j] = fmaf(C3[j], S0[j], fmaf(C2[j], S3[j],
                                 fmaf(C1[j], S2[j], C0[j] * S1[j])));
                } else if (kk == 2) {
                    a = ((S2[0] + S2[1]) + (S2[2] + S2[3]))
                      + ((S2[4] + S2[5]) + (S2[6] + S2[7]));
#pragma unroll
                    for (int j = 0; j < NS; j++)
                        S2[j] = fmaf(C3[j], S1[j], fmaf(C2[j], S0[j],
                                 fmaf(C1[j], S3[j], C0[j] * S2[j])));
                } else {
                    a = ((S3[0] + S3[1]) + (S3[2] + S3[3]))
                      + ((S3[4] + S3[5]) + (S3[6] + S3[7]));
#pragma unroll
                    for (int j = 0; j < NS; j++)
                        S3[j] = fmaf(C3[j], S2[j], fmaf(C2[j], S1[j],
                                 fmaf(C1[j], S0[j], C0[j] * S3[j])));
                }
                s_slot[(size_t)(k4 + kk) * (WARPS * 32)] = a;
            }
        }
        __syncthreads();

        // ---- cross-warp reduction: warp w handles k = w + 4i ----
#pragma unroll
        for (int i = 0; i < CHUNK_K / WARPS; i++) {
            int k = wid + WARPS * i;
            float sum = (s_part[k][0][lane] + s_part[k][1][lane])
                      + (s_part[k][2][lane] + s_part[k][3][lane]);
            orow[(size_t)(ch * CHUNK_K + k) * 32 + lane] = sum;
        }
    }
}

extern "C" void kernel_launch(void* const* d_in, const int* in_sizes, int n_in,
                              void* d_out, int out_size)
{
    const float* log_dt = (const float*)d_in[0];
    const float* C      = (const float*)d_in[1];
    const float* A      = (const float*)d_in[2];
    // d_in[3] = input_length scalar; L derived from out_size.

    int H = in_sizes[0];          // 1024
    int L = out_size / H;         // 2048

    s4d_fused<<<H, 128>>>(log_dt, C, A, (float*)d_out, L);
}

// round 9
// speedup vs baseline: 1.2045x; 1.1100x over previous
#include <cuda_runtime.h>

// S4D kernel: K[h,l] = 2 * Re( sum_n Cmod[h,n] * exp(dtA[h,n] * l) ),
// H=1024, N=64, L=2048.
//
// Modes merged in pairs: s_k = r_k[n] + r_k[n+1] obeys an ORDER-4 real
// recurrence s_{k+4} = c3 s_{k+3} + c2 s_{k+2} + c1 s_{k+1} + c0 s_k
// (char poly = product of the two mode quadratics; all |roots|<1).
//
// One block (128 thr, 4 warps) per h; lane owns l = lane + 32k, 64 k.
// Warp w owns n in [16w,16w+16) = 4 packed f32x2 stream-pairs per thread.
// Per-thread init uses __expf/__sincosf intrinsics (errors enter linearly,
// ~1e-6); per-n coefficient precompute stays precise (root errors amplify
// x64). Partials buffered 16 k at a time (8KB), 4 chunks, barrier-free
// inner loop.

#define N_      64
#define WARPS   4
#define SP      4              // packed stream-pairs per thread
#define CHUNK_K 16             // k-steps per chunk
#define CHUNKS  4

typedef unsigned long long u64;

__device__ __forceinline__ u64 pack2(float lo, float hi) {
    u64 r; asm("mov.b64 %0, {%1,%2};" : "=l"(r) : "f"(lo), "f"(hi)); return r;
}
__device__ __forceinline__ void unpack2(u64 v, float& lo, float& hi) {
    asm("mov.b64 {%0,%1}, %2;" : "=f"(lo), "=f"(hi) : "l"(v));
}
__device__ __forceinline__ u64 fma2(u64 a, u64 b, u64 c) {
    u64 d; asm("fma.rn.f32x2 %0,%1,%2,%3;" : "=l"(d) : "l"(a), "l"(b), "l"(c)); return d;
}
__device__ __forceinline__ u64 mul2(u64 a, u64 b) {
    u64 d; asm("mul.rn.f32x2 %0,%1,%2;" : "=l"(d) : "l"(a), "l"(b)); return d;
}
__device__ __forceinline__ u64 add2(u64 a, u64 b) {
    u64 d; asm("add.rn.f32x2 %0,%1,%2;" : "=l"(d) : "l"(a), "l"(b)); return d;
}

__global__ __launch_bounds__(128)
void s4d_fused(const float* __restrict__ log_dt,
               const float* __restrict__ C,
               const float* __restrict__ A,
               float* __restrict__ out, int L)
{
    __shared__ float2 s_dta[N_], s_cm[N_], s_w32[N_], s_pq[N_];
    __shared__ float4 s_c4[N_ / 2];                 // order-4 coeffs per merged pair
    __shared__ u64    s_part[CHUNK_K][WARPS][32];   // packed partials, 8KB

    const int h    = blockIdx.x;
    const int tid  = threadIdx.x;
    const int wid  = tid >> 5;
    const int lane = tid & 31;

    // ---- per-n parameter precompute (threads 0..63, one n each).
    //      PRECISE math here: coefficient errors shift recurrence roots and
    //      amplify ~64x over the k-steps. ----
    if (tid < N_) {
        int n = tid;
        float dt  = expf(log_dt[h]);
        float ar  = A[2 * n], ai = A[2 * n + 1];
        float dre = dt * ar, dim = dt * ai;

        float e1 = expf(dre); float s1, c1; sincosf(dim, &s1, &c1);
        float w1r = e1 * c1, w1i = e1 * s1;

        float inv = 1.0f / (ar * ar + ai * ai);
        float nr = w1r - 1.0f, ni = w1i;
        float qdr = (nr * ar + ni * ai) * inv;
        float qdi = (ni * ar - nr * ai) * inv;

        float cr = C[2 * (h * N_ + n)], ci = C[2 * (h * N_ + n) + 1];
        float cmr = 2.0f * (cr * qdr - ci * qdi);
        float cmi = 2.0f * (cr * qdi + ci * qdr);

        float e32 = expf(32.0f * dre); float s32, c32; sincosf(32.0f * dim, &s32, &c32);
        float wr = e32 * c32, wi = e32 * s32;

        s_dta[n] = make_float2(dre, dim);
        s_cm [n] = make_float2(cmr, cmi);
        s_w32[n] = make_float2(wr, wi);
        s_pq [n] = make_float2(2.0f * wr, -(wr * wr + wi * wi));
    }
    __syncthreads();

    // ---- merged order-4 coefficients: (x^2 - p1 x - q1)(x^2 - p2 x - q2) ----
    if (tid < N_ / 2) {
        float2 a = s_pq[2 * tid], b = s_pq[2 * tid + 1];
        float c3 = a.x + b.x;
        float c2 = a.y + b.y - a.x * b.x;
        float c1 = -(a.x * b.y + b.x * a.y);
        float c0 = -a.y * b.y;
        s_c4[tid] = make_float4(c0, c1, c2, c3);
    }
    __syncthreads();

    // ---- per-thread state init (FAST intrinsics: errors enter linearly) ----
    const float lf = (float)lane;
    const int   n0 = wid * 16;

    u64 S0[SP], S1[SP], S2[SP], S3[SP];
    u64 C0[SP], C1[SP], C2[SP], C3[SP];

#pragma unroll
    for (int j = 0; j < SP; j++) {
        float sm[2][4];
#pragma unroll
        for (int t = 0; t < 2; t++) {
            int ns = n0 + 2 * (2 * j + t);
            float acc[4] = {0.f, 0.f, 0.f, 0.f};
#pragma unroll
            for (int u = 0; u < 2; u++) {
                int n = ns + u;
                float2 d = s_dta[n];
                float ex = __expf(d.x * lf);
                float s, c; __sincosf(d.y * lf, &s, &c);
                float er = ex * c, ei = ex * s;
                float2 cm = s_cm[n];
                float zr = cm.x * er - cm.y * ei;
                float zi = cm.x * ei + cm.y * er;
                float2 w = s_w32[n];
#pragma unroll
                for (int k = 0; k < 4; k++) {
                    acc[k] += zr;
                    float tr = zr * w.x - zi * w.y;
                    float ti = zr * w.y + zi * w.x;
                    zr = tr; zi = ti;
                }
            }
#pragma unroll
            for (int k = 0; k < 4; k++) sm[t][k] = acc[k];
        }
        S0[j] = pack2(sm[0][0], sm[1][0]);
        S1[j] = pack2(sm[0][1], sm[1][1]);
        S2[j] = pack2(sm[0][2], sm[1][2]);
        S3[j] = pack2(sm[0][3], sm[1][3]);

        float4 ca = s_c4[(n0 >> 1) + 2 * j];
        float4 cb = s_c4[(n0 >> 1) + 2 * j + 1];
        C0[j] = pack2(ca.x, cb.x);
        C1[j] = pack2(ca.y, cb.y);
        C2[j] = pack2(ca.z, cb.z);
        C3[j] = pack2(ca.w, cb.w);
    }

    float* orow  = out + (size_t)h * L;
    u64*   s_slot = &s_part[0][wid][lane];

#pragma unroll 1
    for (int ch = 0; ch < CHUNKS; ch++) {
        if (ch) __syncthreads();            // buffer reusable

#pragma unroll 1
        for (int k4 = 0; k4 < CHUNK_K; k4 += 4) {
#pragma unroll
            for (int kk = 0; kk < 4; kk++) {
                u64 a0, a1;
                if (kk == 0) {
                    a0 = add2(S0[0], S0[1]); a1 = add2(S0[2], S0[3]);
#pragma unroll
                    for (int j = 0; j < SP; j++)
                        S0[j] = fma2(C3[j], S3[j], fma2(C2[j], S2[j],
                                 fma2(C1[j], S1[j], mul2(C0[j], S0[j]))));
                } else if (kk == 1) {
                    a0 = add2(S1[0], S1[1]); a1 = add2(S1[2], S1[3]);
#pragma unroll
                    for (int j = 0; j < SP; j++)
                        S1[j] = fma2(C3[j], S0[j], fma2(C2[j], S3[j],
                                 fma2(C1[j], S2[j], mul2(C0[j], S1[j]))));
                } else if (kk == 2) {
                    a0 = add2(S2[0], S2[1]); a1 = add2(S2[2], S2[3]);
#pragma unroll
                    for (int j = 0; j < SP; j++)
                        S2[j] = fma2(C3[j], S1[j], fma2(C2[j], S0[j],
                                 fma2(C1[j], S3[j], mul2(C0[j], S2[j]))));
                } else {
                    a0 = add2(S3[0], S3[1]); a1 = add2(S3[2], S3[3]);
#pragma unroll
                    for (int j = 0; j < SP; j++)
                        S3[j] = fma2(C3[j], S2[j], fma2(C2[j], S1[j],
                                 fma2(C1[j], S0[j], mul2(C0[j], S3[j]))));
                }
                s_slot[(size_t)(k4 + kk) * (WARPS * 32)] = add2(a0, a1);
            }
        }
        __syncthreads();

        // ---- cross-warp reduction: warp w handles k = w + 4i ----
#pragma unroll
        for (int i = 0; i < CHUNK_K / WARPS; i++) {
            int k = wid + WARPS * i;
            float sum = 0.0f;
#pragma unroll
            for (int w = 0; w < WARPS; w++) {
                float lo, hi;
                unpack2(s_part[k][w][lane], lo, hi);
                sum += lo + hi;
            }
            orow[(size_t)(ch * CHUNK_K + k) * 32 + lane] = sum;
        }
    }
}

extern "C" void kernel_launch(void* const* d_in, const int* in_sizes, int n_in,
                              void* d_out, int out_size)
{
    const float* log_dt = (const float*)d_in[0];
    const float* C      = (const float*)d_in[1];
    const float* A      = (const float*)d_in[2];
    // d_in[3] = input_length scalar; L derived from out_size.

    int H = in_sizes[0];          // 1024
    int L = out_size / H;         // 2048

    s4d_fused<<<H, 128>>>(log_dt, C, A, (float*)d_out, L);
}